// round 9
// baseline (speedup 1.0000x reference)
#include <cuda_runtime.h>

#define SEQ    16384
#define BATCH   1024
#define NWIN      61
#define STEP     256
#define TPB      128                 // threads per CTA (main)

// Weight table: 8 sets x 256 samples (prefix P[0..3] = sets 0..3,
// suffix S[0..3] = sets 4..7), pre-scaled by 1/61, im = -sin/61.
__device__ float g_Wre[8 * 256];
__device__ float g_Wim[8 * 256];

// ---- Kernel 1: build prefix/suffix weight table (1024 sincosf total) ----
// Fires launch_dependents at entry so the main kernel's CTAs launch and begin
// their (table-independent) input loads while this runs.
__global__ void table_kernel(const float* __restrict__ freqs) {
    asm volatile("griddepcontrol.launch_dependents;" ::: "memory");
    const int p0 = threadIdx.x;                 // 0..255
    const float TWO_PI = 6.283185307179586476925f;
    const float inv = 1.0f / (float)NWIN;
    float cr[4], ci[4];
    #pragma unroll
    for (int k = 0; k < 4; ++k) {
        float sn, cs;
        sincosf(TWO_PI * freqs[p0 + STEP * k], &sn, &cs);
        cr[k] = cs * inv;
        ci[k] = -sn * inv;
    }
    float pr = 0.f, pi = 0.f;
    #pragma unroll
    for (int k = 0; k < 4; ++k) {               // prefixes P[k]
        pr += cr[k]; pi += ci[k];
        g_Wre[k * 256 + p0] = pr;
        g_Wim[k * 256 + p0] = pi;
    }
    float sr = 0.f, si = 0.f;
    #pragma unroll
    for (int k = 3; k >= 0; --k) {              // suffixes S[k]
        sr += cr[k]; si += ci[k];
        g_Wre[(4 + k) * 256 + p0] = sr;
        g_Wim[(4 + k) * 256 + p0] = si;
    }
}

// ---- Kernel 2: one CTA per batch row; whole grid resident in one wave ----
// Thread tid owns float4 groups l = tid + 128g (g=0..31); sample s = 4l+c.
// s mod 256 = 4*(tid&63)+c (g-invariant); wbase = s>>8 = (tid>>6) + 2g.
//   g==0  -> P[q]   g==1 -> P[2+q]   g==30 -> S[q]   g==31 -> S[2+q]
//   g==2..29 -> P[3] (interior full sum; S[0]==P[3] handles wbase=60)
__global__ __launch_bounds__(TPB, 8) void welch_kernel(
    const float4* __restrict__ in,
    const float*  __restrict__ fc_w,
    const float*  __restrict__ fc_b,
    float*        __restrict__ out)
{
    const int tid = threadIdx.x;
    const int b   = blockIdx.x;
    const int q   = tid >> 6;        // 0 or 1
    const int j   = tid & 63;        // float4 index within 256-sample period

    const float4* __restrict__ row  = in + (size_t)b * (SEQ / 4) + tid;

    // ---- Prefetch edge input groups BEFORE waiting on the table grid ----
    float4 xe0 = __ldcg(row +  0 * TPB);
    float4 xe1 = __ldcg(row +  1 * TPB);
    float4 xe2 = __ldcg(row + 30 * TPB);
    float4 xe3 = __ldcg(row + 31 * TPB);

    // Wait for table_kernel completion + memory visibility.
    asm volatile("griddepcontrol.wait;" ::: "memory");

    const float4* __restrict__ Wre4 = (const float4*)g_Wre;
    const float4* __restrict__ Wim4 = (const float4*)g_Wim;

    float re0 = 0.f, re1 = 0.f, im0 = 0.f, im1 = 0.f;

    // ---- Edge phase: groups 0, 1, 30, 31 (weights short-lived) ----
    {
        float4 Ar = Wre4[(0 + q) * 64 + j], Ai = Wim4[(0 + q) * 64 + j];
        float4 Br = Wre4[(2 + q) * 64 + j], Bi = Wim4[(2 + q) * 64 + j];
        float4 Cr = Wre4[(4 + q) * 64 + j], Ci = Wim4[(4 + q) * 64 + j];
        float4 Dr = Wre4[(6 + q) * 64 + j], Di = Wim4[(6 + q) * 64 + j];

        re0 = fmaf(xe0.x, Ar.x, re0); re0 = fmaf(xe0.y, Ar.y, re0);
        re0 = fmaf(xe0.z, Ar.z, re0); re0 = fmaf(xe0.w, Ar.w, re0);
        im0 = fmaf(xe0.x, Ai.x, im0); im0 = fmaf(xe0.y, Ai.y, im0);
        im0 = fmaf(xe0.z, Ai.z, im0); im0 = fmaf(xe0.w, Ai.w, im0);

        re1 = fmaf(xe1.x, Br.x, re1); re1 = fmaf(xe1.y, Br.y, re1);
        re1 = fmaf(xe1.z, Br.z, re1); re1 = fmaf(xe1.w, Br.w, re1);
        im1 = fmaf(xe1.x, Bi.x, im1); im1 = fmaf(xe1.y, Bi.y, im1);
        im1 = fmaf(xe1.z, Bi.z, im1); im1 = fmaf(xe1.w, Bi.w, im1);

        re0 = fmaf(xe2.x, Cr.x, re0); re0 = fmaf(xe2.y, Cr.y, re0);
        re0 = fmaf(xe2.z, Cr.z, re0); re0 = fmaf(xe2.w, Cr.w, re0);
        im0 = fmaf(xe2.x, Ci.x, im0); im0 = fmaf(xe2.y, Ci.y, im0);
        im0 = fmaf(xe2.z, Ci.z, im0); im0 = fmaf(xe2.w, Ci.w, im0);

        re1 = fmaf(xe3.x, Dr.x, re1); re1 = fmaf(xe3.y, Dr.y, re1);
        re1 = fmaf(xe3.z, Dr.z, re1); re1 = fmaf(xe3.w, Dr.w, re1);
        im1 = fmaf(xe3.x, Di.x, im1); im1 = fmaf(xe3.y, Di.y, im1);
        im1 = fmaf(xe3.z, Di.z, im1); im1 = fmaf(xe3.w, Di.w, im1);
    }

    // ---- Interior phase: groups 2..29, shared weight, 7-deep batches ----
    const float4 Ir = Wre4[3 * 64 + j];
    const float4 Ii = Wim4[3 * 64 + j];

    #pragma unroll
    for (int bt = 0; bt < 4; ++bt) {
        float4 x[7];
        #pragma unroll
        for (int i = 0; i < 7; ++i)
            x[i] = __ldcg(row + (2 + 7 * bt + i) * TPB);

        #pragma unroll
        for (int i = 0; i < 7; ++i) {
            if (i & 1) {
                re1 = fmaf(x[i].x, Ir.x, re1); re1 = fmaf(x[i].y, Ir.y, re1);
                re1 = fmaf(x[i].z, Ir.z, re1); re1 = fmaf(x[i].w, Ir.w, re1);
                im1 = fmaf(x[i].x, Ii.x, im1); im1 = fmaf(x[i].y, Ii.y, im1);
                im1 = fmaf(x[i].z, Ii.z, im1); im1 = fmaf(x[i].w, Ii.w, im1);
            } else {
                re0 = fmaf(x[i].x, Ir.x, re0); re0 = fmaf(x[i].y, Ir.y, re0);
                re0 = fmaf(x[i].z, Ir.z, re0); re0 = fmaf(x[i].w, Ir.w, re0);
                im0 = fmaf(x[i].x, Ii.x, im0); im0 = fmaf(x[i].y, Ii.y, im0);
                im0 = fmaf(x[i].z, Ii.z, im0); im0 = fmaf(x[i].w, Ii.w, im0);
            }
        }
    }

    float re = re0 + re1;
    float im = im0 + im1;

    // Block reduce: 4 warps -> 1 value.
    #pragma unroll
    for (int off = 16; off > 0; off >>= 1) {
        re += __shfl_xor_sync(0xffffffffu, re, off);
        im += __shfl_xor_sync(0xffffffffu, im, off);
    }
    __shared__ float s[8];
    const int w    = tid >> 5;
    const int lane = tid & 31;
    if (lane == 0) { s[w] = re; s[4 + w] = im; }
    __syncthreads();

    if (tid == 0) {
        float fr = (s[0] + s[1]) + (s[2] + s[3]);
        float fi = (s[4] + s[5]) + (s[6] + s[7]);
        float psd = fr * fr + fi * fi;
        out[b] = fmaf(psd, fc_w[0], fc_b[0]);
    }
}

extern "C" void kernel_launch(void* const* d_in, const int* in_sizes, int n_in,
                              void* d_out, int out_size) {
    const float* input = (const float*)d_in[0];   // (1024, 16384) f32
    const float* freqs = (const float*)d_in[1];   // (1024,) f32
    const float* fc_w  = (const float*)d_in[2];   // (1,1) f32
    const float* fc_b  = (const float*)d_in[3];   // (1,) f32
    float* out = (float*)d_out;                   // (1024, 1) f32

    table_kernel<<<1, 256>>>(freqs);

    // Launch welch with programmatic dependent launch so its CTAs spin up
    // (and start input loads) while table_kernel is still running.
    cudaLaunchConfig_t cfg = {};
    cfg.gridDim  = dim3(BATCH, 1, 1);
    cfg.blockDim = dim3(TPB, 1, 1);
    cfg.dynamicSmemBytes = 0;
    cfg.stream = 0;
    cudaLaunchAttribute attr[1];
    attr[0].id = cudaLaunchAttributeProgrammaticStreamSerialization;
    attr[0].val.programmaticStreamSerializationAllowed = 1;
    cfg.attrs = attr;
    cfg.numAttrs = 1;
    cudaLaunchKernelEx(&cfg, welch_kernel,
                       (const float4*)input, fc_w, fc_b, out);
}

// round 10
// speedup vs baseline: 1.0239x; 1.0239x over previous
#include <cuda_runtime.h>

#define SEQ    16384
#define BATCH   1024
#define NWIN      61
#define STEP     256
#define TPB      128                 // threads per CTA

// Single fused kernel: one CTA per batch row; whole grid resident in one wave.
// Thread tid owns float4 groups l = tid + 128g (g=0..31); sample s = 4l+c.
// s mod 256 = 4*(tid&63)+c (g-invariant); wbase = s>>8 = (tid>>6) + 2g.
// Collapsed weight for sample s = (1/61) * sum over valid k of
//   (cos, -sin)(2*pi*freqs[(s mod 256) + 256k]),  valid iff 0 <= wbase-k < 61.
//   g==0  -> prefix P[q]   g==1 -> P[2+q]       (q = tid>>6)
//   g==30 -> suffix S[q]   g==31 -> S[2+q]
//   g==2..29 -> full sum (P[3] == S[0])
__global__ __launch_bounds__(TPB, 7) void welch_kernel(
    const float4* __restrict__ in,
    const float*  __restrict__ freqs,
    const float*  __restrict__ fc_w,
    const float*  __restrict__ fc_b,
    float*        __restrict__ out)
{
    __shared__ float s_cos[1024];
    __shared__ float s_sin[1024];    // holds -sin/61; s_cos holds cos/61
    __shared__ float s_red[8];

    const int tid = threadIdx.x;
    const int b   = blockIdx.x;
    const int q   = tid >> 6;        // 0 or 1
    const int j   = tid & 63;        // float4 index within 256-sample period
    const int pb  = 4 * j;

    const float4* __restrict__ row = in + (size_t)b * (SEQ / 4) + tid;

    // ---- Prefetch edge input groups: DRAM busy during the trig prologue ----
    float4 xe0 = __ldcg(row +  0 * TPB);
    float4 xe1 = __ldcg(row +  1 * TPB);
    float4 xe2 = __ldcg(row + 30 * TPB);
    float4 xe3 = __ldcg(row + 31 * TPB);

    // ---- Trig table: 8 fast sincos per thread (MUFU), 1024 bins total ----
    const float TWO_PI = 6.283185307179586476925f;
    const float inv = 1.0f / (float)NWIN;
    #pragma unroll
    for (int k = 0; k < 8; ++k) {
        int p = tid + k * TPB;
        float sn, cs;
        __sincosf(TWO_PI * freqs[p], &sn, &cs);
        s_cos[p] = cs * inv;
        s_sin[p] = -sn * inv;
    }
    __syncthreads();

    // ---- Build weight sets in registers (prefix/suffix over k) ----
    const float4* __restrict__ c4 = (const float4*)s_cos;
    const float4* __restrict__ i4 = (const float4*)s_sin;
    // t_k = (cos,-sin)/61 at bins pb..pb+3 + 256k
    float4 c0 = c4[j +   0], s0 = i4[j +   0];
    float4 c1 = c4[j +  64], s1 = i4[j +  64];
    float4 c2 = c4[j + 128], s2 = i4[j + 128];
    float4 c3 = c4[j + 192], s3 = i4[j + 192];

    float re0 = 0.f, re1 = 0.f, im0 = 0.f, im1 = 0.f;

    // A = P[q]: q==0 -> t0, q==1 -> t0+t1. Consume with xe0 immediately.
    {
        float4 ar, ai;
        ar.x = q ? c0.x + c1.x : c0.x;  ai.x = q ? s0.x + s1.x : s0.x;
        ar.y = q ? c0.y + c1.y : c0.y;  ai.y = q ? s0.y + s1.y : s0.y;
        ar.z = q ? c0.z + c1.z : c0.z;  ai.z = q ? s0.z + s1.z : s0.z;
        ar.w = q ? c0.w + c1.w : c0.w;  ai.w = q ? s0.w + s1.w : s0.w;
        re0 = fmaf(xe0.x, ar.x, re0); re0 = fmaf(xe0.y, ar.y, re0);
        re0 = fmaf(xe0.z, ar.z, re0); re0 = fmaf(xe0.w, ar.w, re0);
        im0 = fmaf(xe0.x, ai.x, im0); im0 = fmaf(xe0.y, ai.y, im0);
        im0 = fmaf(xe0.z, ai.z, im0); im0 = fmaf(xe0.w, ai.w, im0);
    }

    // Full sum I = t0+t1+t2+t3 (also P[3] and S[0]); partial pr3 = t0+t1+t2.
    float4 Ir, Ii, pr3r, pr3i;
    pr3r.x = c0.x + c1.x + c2.x;  pr3i.x = s0.x + s1.x + s2.x;
    pr3r.y = c0.y + c1.y + c2.y;  pr3i.y = s0.y + s1.y + s2.y;
    pr3r.z = c0.z + c1.z + c2.z;  pr3i.z = s0.z + s1.z + s2.z;
    pr3r.w = c0.w + c1.w + c2.w;  pr3i.w = s0.w + s1.w + s2.w;
    Ir.x = pr3r.x + c3.x;  Ii.x = pr3i.x + s3.x;
    Ir.y = pr3r.y + c3.y;  Ii.y = pr3i.y + s3.y;
    Ir.z = pr3r.z + c3.z;  Ii.z = pr3i.z + s3.z;
    Ir.w = pr3r.w + c3.w;  Ii.w = pr3i.w + s3.w;

    // B = P[2+q]: q==0 -> pr3, q==1 -> I. Consume with xe1.
    {
        float4 br, bi;
        br.x = q ? Ir.x : pr3r.x;  bi.x = q ? Ii.x : pr3i.x;
        br.y = q ? Ir.y : pr3r.y;  bi.y = q ? Ii.y : pr3i.y;
        br.z = q ? Ir.z : pr3r.z;  bi.z = q ? Ii.z : pr3i.z;
        br.w = q ? Ir.w : pr3r.w;  bi.w = q ? Ii.w : pr3i.w;
        re1 = fmaf(xe1.x, br.x, re1); re1 = fmaf(xe1.y, br.y, re1);
        re1 = fmaf(xe1.z, br.z, re1); re1 = fmaf(xe1.w, br.w, re1);
        im1 = fmaf(xe1.x, bi.x, im1); im1 = fmaf(xe1.y, bi.y, im1);
        im1 = fmaf(xe1.z, bi.z, im1); im1 = fmaf(xe1.w, bi.w, im1);
    }

    // Suffixes: S2 = t2+t3, S1 = t1+S2. C = S[q] (q?S1:I), D = S[2+q] (q?t3:S2).
    {
        float4 s2r, s2i, s1r, s1i;
        s2r.x = c2.x + c3.x;  s2i.x = s2.x + s3.x;
        s2r.y = c2.y + c3.y;  s2i.y = s2.y + s3.y;
        s2r.z = c2.z + c3.z;  s2i.z = s2.z + s3.z;
        s2r.w = c2.w + c3.w;  s2i.w = s2.w + s3.w;
        s1r.x = c1.x + s2r.x; s1i.x = s1.x + s2i.x;
        s1r.y = c1.y + s2r.y; s1i.y = s1.y + s2i.y;
        s1r.z = c1.z + s2r.z; s1i.z = s1.z + s2i.z;
        s1r.w = c1.w + s2r.w; s1i.w = s1.w + s2i.w;

        float4 cr, ci;
        cr.x = q ? s1r.x : Ir.x;  ci.x = q ? s1i.x : Ii.x;
        cr.y = q ? s1r.y : Ir.y;  ci.y = q ? s1i.y : Ii.y;
        cr.z = q ? s1r.z : Ir.z;  ci.z = q ? s1i.z : Ii.z;
        cr.w = q ? s1r.w : Ir.w;  ci.w = q ? s1i.w : Ii.w;
        re0 = fmaf(xe2.x, cr.x, re0); re0 = fmaf(xe2.y, cr.y, re0);
        re0 = fmaf(xe2.z, cr.z, re0); re0 = fmaf(xe2.w, cr.w, re0);
        im0 = fmaf(xe2.x, ci.x, im0); im0 = fmaf(xe2.y, ci.y, im0);
        im0 = fmaf(xe2.z, ci.z, im0); im0 = fmaf(xe2.w, ci.w, im0);

        float4 dr, di;
        dr.x = q ? c3.x : s2r.x;  di.x = q ? s3.x : s2i.x;
        dr.y = q ? c3.y : s2r.y;  di.y = q ? s3.y : s2i.y;
        dr.z = q ? c3.z : s2r.z;  di.z = q ? s3.z : s2i.z;
        dr.w = q ? c3.w : s2r.w;  di.w = q ? s3.w : s2i.w;
        re1 = fmaf(xe3.x, dr.x, re1); re1 = fmaf(xe3.y, dr.y, re1);
        re1 = fmaf(xe3.z, dr.z, re1); re1 = fmaf(xe3.w, dr.w, re1);
        im1 = fmaf(xe3.x, di.x, im1); im1 = fmaf(xe3.y, di.y, im1);
        im1 = fmaf(xe3.z, di.z, im1); im1 = fmaf(xe3.w, di.w, im1);
    }

    // ---- Interior phase: groups 2..29, shared weight Ir/Ii, 7-deep batches ----
    #pragma unroll
    for (int bt = 0; bt < 4; ++bt) {
        float4 x[7];
        #pragma unroll
        for (int i = 0; i < 7; ++i)
            x[i] = __ldcg(row + (2 + 7 * bt + i) * TPB);

        #pragma unroll
        for (int i = 0; i < 7; ++i) {
            if (i & 1) {
                re1 = fmaf(x[i].x, Ir.x, re1); re1 = fmaf(x[i].y, Ir.y, re1);
                re1 = fmaf(x[i].z, Ir.z, re1); re1 = fmaf(x[i].w, Ir.w, re1);
                im1 = fmaf(x[i].x, Ii.x, im1); im1 = fmaf(x[i].y, Ii.y, im1);
                im1 = fmaf(x[i].z, Ii.z, im1); im1 = fmaf(x[i].w, Ii.w, im1);
            } else {
                re0 = fmaf(x[i].x, Ir.x, re0); re0 = fmaf(x[i].y, Ir.y, re0);
                re0 = fmaf(x[i].z, Ir.z, re0); re0 = fmaf(x[i].w, Ir.w, re0);
                im0 = fmaf(x[i].x, Ii.x, im0); im0 = fmaf(x[i].y, Ii.y, im0);
                im0 = fmaf(x[i].z, Ii.z, im0); im0 = fmaf(x[i].w, Ii.w, im0);
            }
        }
    }

    float re = re0 + re1;
    float im = im0 + im1;

    // ---- Block reduce: 4 warps -> 1 value ----
    #pragma unroll
    for (int off = 16; off > 0; off >>= 1) {
        re += __shfl_xor_sync(0xffffffffu, re, off);
        im += __shfl_xor_sync(0xffffffffu, im, off);
    }
    const int w    = tid >> 5;
    const int lane = tid & 31;
    if (lane == 0) { s_red[w] = re; s_red[4 + w] = im; }
    __syncthreads();

    if (tid == 0) {
        float fr = (s_red[0] + s_red[1]) + (s_red[2] + s_red[3]);
        float fi = (s_red[4] + s_red[5]) + (s_red[6] + s_red[7]);
        float psd = fr * fr + fi * fi;
        out[b] = fmaf(psd, fc_w[0], fc_b[0]);
    }
}

extern "C" void kernel_launch(void* const* d_in, const int* in_sizes, int n_in,
                              void* d_out, int out_size) {
    const float* input = (const float*)d_in[0];   // (1024, 16384) f32
    const float* freqs = (const float*)d_in[1];   // (1024,) f32
    const float* fc_w  = (const float*)d_in[2];   // (1,1) f32
    const float* fc_b  = (const float*)d_in[3];   // (1,) f32
    float* out = (float*)d_out;                   // (1024, 1) f32

    welch_kernel<<<BATCH, TPB>>>((const float4*)input, freqs, fc_w, fc_b, out);
}